// round 17
// baseline (speedup 1.0000x reference)
#include <cuda_runtime.h>
#include <cuda_fp16.h>
#include <cstdint>

#define NN 50000
#define NNP 50048
#define EE 400000
#define DD 300
#define KP 304
#define KP2 152
#define KU4 38
#define WNP 320
#define LL 5
#define CC 128
#define NGR 256
#define BN_EPS 1e-5f

#define BM 128
#define BN 160
#define NCH 19
#define MT ((NNP) / BM)        // 391
#define GRIDY 148
#define LDB 168
#define SMEMSZ (KP * LDB * 2)  // 102144: full B tile resident

// ---------------- static device scratch ----------------
__device__ int   g_is64;
__device__ int   g_cnt[NN];
__device__ int   g_off[NN + 1];
__device__ int   g_pos[NN];
__device__ int   g_srcl[EE];
__device__ int   g_goff[NGR + 1];
__device__ int   g_bsum[128];
__device__ int   g_bpre[128];
__device__ __align__(16) __half g_z0h[(size_t)NN * DD];   // GEMM2 out
__device__ __align__(16) __half g_z1h[(size_t)NN * DD];   // GEMM1 out
__device__ __align__(16) __half g_hbuf[(size_t)NN * KP];  // bnrelu'd h / fp16(x), padded
__device__ __align__(16) __half g_a[(size_t)NNP * KP];    // GEMM A operand
__device__ __align__(16) __half g_w[(size_t)2 * LL * KP * WNP];
__device__ float g_colsum[DD];
__device__ float g_colsq[DD];
__device__ __align__(16) __half g_sc1h[DD], g_sh1h[DD], g_sc2h[DD], g_sh2h[DD];
__device__ __align__(16) float g_pooled[(size_t)(LL + 1) * NGR * DD];

// ---------------- PTX helpers ----------------
__device__ __forceinline__ void gdep_wait() {
    asm volatile("griddepcontrol.wait;" ::: "memory");
}
__device__ __forceinline__ uint32_t smem_u32(const void* p) {
    uint32_t a;
    asm("{ .reg .u64 t; cvta.to.shared.u64 t, %1; cvt.u32.u64 %0, t; }" : "=r"(a) : "l"(p));
    return a;
}
__device__ __forceinline__ void cp16(uint32_t d, const void* s) {
    asm volatile("cp.async.cg.shared.global [%0], [%1], 16;" :: "r"(d), "l"(s) : "memory");
}
__device__ __forceinline__ void cp_commit() {
    asm volatile("cp.async.commit_group;" ::: "memory");
}
__device__ __forceinline__ void cp_wait0() {
    asm volatile("cp.async.wait_group 0;" ::: "memory");
}
__device__ __forceinline__ void ldsm_x2t(uint32_t* r, uint32_t addr) {
    asm volatile("ldmatrix.sync.aligned.m8n8.x2.trans.shared.b16 {%0,%1}, [%2];"
                 : "=r"(r[0]), "=r"(r[1]) : "r"(addr));
}
__device__ __forceinline__ void mma16816(float* d, const uint32_t* a, const uint32_t* b) {
    asm volatile("mma.sync.aligned.m16n8k16.row.col.f32.f16.f16.f32 "
                 "{%0,%1,%2,%3}, {%4,%5,%6,%7}, {%8,%9}, {%0,%1,%2,%3};"
                 : "+f"(d[0]), "+f"(d[1]), "+f"(d[2]), "+f"(d[3])
                 : "r"(a[0]), "r"(a[1]), "r"(a[2]), "r"(a[3]), "r"(b[0]), "r"(b[1]));
}
__device__ __forceinline__ int idx_at(const void* p, long long i) {
    if (g_is64) return (int)((const long long*)p)[i];
    return ((const int*)p)[i];
}

// ---------------- setup kernels ----------------
__global__ void k_zero(const void* ei) {
    gdep_wait();
    int i = blockIdx.x * blockDim.x + threadIdx.x;
    if (i == 0) {
        const int* w = (const int*)ei;
        int all0 = 1;
        for (int q = 0; q < 128; q++)
            if (w[2 * q + 1] != 0) { all0 = 0; break; }
        g_is64 = all0;
    }
    if (i < NN) g_cnt[i] = 0;
    if (i < DD) { g_colsum[i] = 0.f; g_colsq[i] = 0.f; }
}

__global__ void k_wprep(const float* __restrict__ W1, const float* __restrict__ b1,
                        const float* __restrict__ W2, const float* __restrict__ b2) {
    gdep_wait();
    int lw = blockIdx.x / KP;
    int k  = blockIdx.x % KP;
    int n  = threadIdx.x;
    int layer = lw >> 1;
    const float* W = (lw & 1) ? W2 : W1;
    const float* b = (lw & 1) ? b2 : b1;
    float v = 0.f;
    if (n < DD) {
        if (k < DD)       v = W[(size_t)layer * DD * DD + (size_t)k * DD + n];
        else if (k == DD) v = b[layer * DD + n];
    }
    g_w[(size_t)lw * KP * WNP + (size_t)k * WNP + n] = __float2half_rn(v);
}

// fp16(x) -> g_hbuf (KP stride, pad cols zeroed) + zero g_a tail rows
__global__ void k_xhalf(const float* __restrict__ x) {
    gdep_wait();
    long long idx = (long long)blockIdx.x * 256 + threadIdx.x;
    const long long NXH = (long long)NN * KP2;
    if (idx < NXH) {
        int row = (int)(idx / KP2), c2 = (int)(idx - (long long)row * KP2);
        __half2 v = __floats2half2_rn(0.f, 0.f);
        if (c2 < 150) {
            float2 f = *(const float2*)(x + (size_t)row * DD + 2 * c2);
            v = __floats2half2_rn(f.x, f.y);
        }
        *(__half2*)(g_hbuf + (size_t)row * KP + 2 * c2) = v;
    } else {
        long long j = idx - NXH;
        if (j < (long long)(NNP - NN) * KU4) {
            int row = NN + (int)(j / KU4), s = (int)(j % KU4);
            ((uint4*)g_a)[(size_t)row * KU4 + s] = make_uint4(0, 0, 0, 0);
        }
    }
}

__global__ void k_count(const void* __restrict__ ei) {
    gdep_wait();
    int e = blockIdx.x * blockDim.x + threadIdx.x;
    if (e < EE) {
        int d = idx_at(ei, (long long)EE + e);
        d = max(0, min(NN - 1, d));
        atomicAdd(&g_cnt[d], 1);
    }
}

__global__ void k_scan1() {
    gdep_wait();
    __shared__ int s[512];
    int b = blockIdx.x, t = threadIdx.x, i = b * 512 + t;
    int v = (i < NN) ? g_cnt[i] : 0;
    s[t] = v;
    __syncthreads();
    for (int d = 1; d < 512; d <<= 1) {
        int y = (t >= d) ? s[t - d] : 0;
        __syncthreads();
        s[t] += y;
        __syncthreads();
    }
    if (i < NN) g_cnt[i] = s[t] - v;
    if (t == 511) g_bsum[b] = s[511];
}
__global__ void k_scan2(int nb) {
    gdep_wait();
    __shared__ int s[128];
    int t = threadIdx.x;
    int v = (t < nb) ? g_bsum[t] : 0;
    s[t] = v;
    __syncthreads();
    for (int d = 1; d < 128; d <<= 1) {
        int y = (t >= d) ? s[t - d] : 0;
        __syncthreads();
        s[t] += y;
        __syncthreads();
    }
    if (t < nb) g_bpre[t] = s[t] - v;
    if (t == nb - 1) g_off[NN] = s[t];
}
__global__ void k_scan3(const void* __restrict__ batch) {
    gdep_wait();
    int i = blockIdx.x * blockDim.x + threadIdx.x;
    if (i < NN) {
        int e = g_bpre[i >> 9] + g_cnt[i];
        g_off[i] = e;
        g_pos[i] = e;
    }
    if (blockIdx.x >= gridDim.x - 2) {
        int g = (blockIdx.x - (gridDim.x - 2)) * blockDim.x + threadIdx.x;
        if (g <= NGR) {
            int lo = 0, hi = NN;
            while (lo < hi) {
                int mid = (lo + hi) >> 1;
                if (idx_at(batch, mid) < g) lo = mid + 1; else hi = mid;
            }
            g_goff[g] = lo;
        }
    }
}

__global__ void k_fill(const void* __restrict__ ei) {
    gdep_wait();
    int e = blockIdx.x * blockDim.x + threadIdx.x;
    if (e < EE) {
        int d = idx_at(ei, (long long)EE + e);
        d = max(0, min(NN - 1, d));
        int srcv = idx_at(ei, e);
        srcv = max(0, min(NN - 1, srcv));
        int p = atomicAdd(&g_pos[d], 1);
        if (p >= 0 && p < EE) g_srcl[p] = srcv;
    }
}

// ---------------- aggregation: warp/node, uint4 + HADD2 ----------------
__global__ void __launch_bounds__(256) k_agg() {
    gdep_wait();
    int w = blockIdx.x * 8 + (threadIdx.x >> 5);
    int lane = threadIdx.x & 31;
    if (w >= NN) return;
    const uint4* hb = (const uint4*)g_hbuf;
    const uint4* rowp = hb + (size_t)w * KU4;
    bool hasB = lane < (KU4 - 32);   // lanes 0..5

    uint4 va = rowp[lane];
    uint4 vb = hasB ? rowp[32 + lane] : make_uint4(0, 0, 0, 0);
    __half2 aA[4], aB[4];
    *(uint4*)aA = va;
    *(uint4*)aB = vb;

    int s0 = g_off[w], s1 = g_off[w + 1];
    s0 = max(0, min(EE, s0));
    s1 = max(s0, min(EE, s1));

    for (int j = s0; j < s1; j++) {
        int src = g_srcl[j];
        const uint4* r2 = hb + (size_t)src * KU4;
        uint4 u = r2[lane];
        __half2* up = (__half2*)&u;
        aA[0] = __hadd2(aA[0], up[0]);
        aA[1] = __hadd2(aA[1], up[1]);
        aA[2] = __hadd2(aA[2], up[2]);
        aA[3] = __hadd2(aA[3], up[3]);
        if (hasB) {
            uint4 u2 = r2[32 + lane];
            __half2* vp = (__half2*)&u2;
            aB[0] = __hadd2(aB[0], vp[0]);
            aB[1] = __hadd2(aB[1], vp[1]);
            aB[2] = __hadd2(aB[2], vp[2]);
            aB[3] = __hadd2(aB[3], vp[3]);
        }
    }

    if (lane == 5) {
        aB[2] = __floats2half2_rn(1.f, 0.f);
        aB[3] = __floats2half2_rn(0.f, 0.f);
    }

    uint4* ar = (uint4*)g_a + (size_t)w * KU4;
    ar[lane] = *(uint4*)aA;
    if (hasB) ar[32 + lane] = *(uint4*)aB;
}

// ---------------- persistent-B fp16 GEMM: B resident in smem, A via LDG ----------------
__global__ void __launch_bounds__(256, 2) k_gemm(int widx, int phase) {
    gdep_wait();
    extern __shared__ __align__(16) char smem[];
    __half* BS = (__half*)smem;            // [KP][LDB] full weight tile

    __half* __restrict__ C = phase ? g_z0h : g_z1h;
    const __half* __restrict__ W = g_w + (size_t)widx * KP * WNP;

    int tid = threadIdx.x, lane = tid & 31, wid = tid >> 5;
    int warp_m = wid & 1, warp_n = wid >> 1;
    int n0 = blockIdx.x * BN;

    // load entire B tile once (6080 cp16 across 256 threads)
    for (int u = tid; u < KP * 20; u += 256) {
        int br = u / 20, bc = u % 20;
        cp16(smem_u32(BS + br * LDB + bc * 8), W + (size_t)br * WNP + n0 + bc * 8);
    }
    cp_commit();
    cp_wait0();
    __syncthreads();

    int lr = lane & 15;
    int rsel = lane >> 2;           // fragment row within 8
    int csel = (lane & 3) * 2;      // fragment col pair

    for (int mt = blockIdx.y; mt < MT; mt += GRIDY) {
        int m0 = mt * BM;
        float acc[4][5][4];
        #pragma unroll
        for (int mi = 0; mi < 4; mi++)
            #pragma unroll
            for (int ni = 0; ni < 5; ni++)
                #pragma unroll
                for (int q = 0; q < 4; q++) acc[mi][ni][q] = 0.f;

        const __half* abase = g_a + (size_t)(m0 + warp_m * 64 + rsel) * KP + csel;

        for (int ch = 0; ch < NCH; ch++) {
            int k0 = ch * 16;
            uint32_t bh[5][2];
            #pragma unroll
            for (int ni = 0; ni < 5; ni++)
                ldsm_x2t(bh[ni], smem_u32(BS + (k0 + lr) * LDB + warp_n * 40 + ni * 8));

            #pragma unroll
            for (int mi = 0; mi < 4; mi++) {
                const __half* ap = abase + (size_t)(mi * 16) * KP + k0;
                uint32_t a[4];
                a[0] = *(const uint32_t*)(ap);
                a[1] = *(const uint32_t*)(ap + (size_t)8 * KP);
                a[2] = *(const uint32_t*)(ap + 8);
                a[3] = *(const uint32_t*)(ap + (size_t)8 * KP + 8);
                #pragma unroll
                for (int ni = 0; ni < 5; ni++)
                    mma16816(acc[mi][ni], a, bh[ni]);
            }
        }

        // epilogue: fp16 store + fp32 column stats (bias folded via K-row)
        float se[5], so[5], qe[5], qo[5];
        #pragma unroll
        for (int ni = 0; ni < 5; ni++) { se[ni] = so[ni] = qe[ni] = qo[ni] = 0.f; }

        #pragma unroll
        for (int mi = 0; mi < 4; mi++) {
            int r0 = m0 + warp_m * 64 + mi * 16 + (lane >> 2);
            int r1 = r0 + 8;
            bool v0 = r0 < NN, v1 = r1 < NN;
            #pragma unroll
            for (int ni = 0; ni < 5; ni++) {
                int gn = n0 + warp_n * 40 + ni * 8 + (lane & 3) * 2;
                bool vc = gn < DD;
                float o0 = acc[mi][ni][0], o1 = acc[mi][ni][1];
                float o2 = acc[mi][ni][2], o3 = acc[mi][ni][3];
                if (v0 && vc) *(__half2*)(C + (size_t)r0 * DD + gn) = __floats2half2_rn(o0, o1);
                if (v1 && vc) *(__half2*)(C + (size_t)r1 * DD + gn) = __floats2half2_rn(o2, o3);
                if (v0) { se[ni] += o0; so[ni] += o1; qe[ni] += o0 * o0; qo[ni] += o1 * o1; }
                if (v1) { se[ni] += o2; so[ni] += o3; qe[ni] += o2 * o2; qo[ni] += o3 * o3; }
            }
        }
        #pragma unroll
        for (int ni = 0; ni < 5; ni++) {
            #pragma unroll
            for (int d = 4; d < 32; d <<= 1) {
                se[ni] += __shfl_xor_sync(0xffffffffu, se[ni], d);
                so[ni] += __shfl_xor_sync(0xffffffffu, so[ni], d);
                qe[ni] += __shfl_xor_sync(0xffffffffu, qe[ni], d);
                qo[ni] += __shfl_xor_sync(0xffffffffu, qo[ni], d);
            }
        }
        if (lane < 4) {
            #pragma unroll
            for (int ni = 0; ni < 5; ni++) {
                int gn = n0 + warp_n * 40 + ni * 8 + lane * 2;
                if (gn < DD) {
                    atomicAdd(&g_colsum[gn], se[ni]);
                    atomicAdd(&g_colsum[gn + 1], so[ni]);
                    atomicAdd(&g_colsq[gn], qe[ni]);
                    atomicAdd(&g_colsq[gn + 1], qo[ni]);
                }
            }
        }
    }
}

__global__ void k_finalize(int phase, const float* __restrict__ gam,
                           const float* __restrict__ bet) {
    gdep_wait();
    int i = threadIdx.x;
    if (i >= DD) return;
    float m = g_colsum[i] * (1.f / NN);
    float v = g_colsq[i] * (1.f / NN) - m * m;
    float r = rsqrtf(v + BN_EPS);
    float sc = r * gam[i];
    float sh = bet[i] - m * sc;
    if (phase == 0) { g_sc1h[i] = __float2half_rn(sc); g_sh1h[i] = __float2half_rn(sh); }
    else            { g_sc2h[i] = __float2half_rn(sc); g_sh2h[i] = __float2half_rn(sh); }
    g_colsum[i] = 0.f;
    g_colsq[i] = 0.f;
}

// relu(z1h*sc1+sh1) -> g_a (GEMM2 input), uint2-vectorized
__global__ void k_bnsplit() {
    gdep_wait();
    int idx = blockIdx.x * 256 + threadIdx.x;
    if (idx >= NN * 75) return;
    int row = idx / 75, c4 = idx - row * 75;
    uint2 z = *(const uint2*)(g_z1h + (size_t)row * DD + 4 * c4);
    uint2 scu = *(const uint2*)(g_sc1h + 4 * c4);
    uint2 shu = *(const uint2*)(g_sh1h + 4 * c4);
    __half2* zp = (__half2*)&z;
    __half2* scp = (__half2*)&scu;
    __half2* shp = (__half2*)&shu;
    __half2 zero = __floats2half2_rn(0.f, 0.f);
    uint2 o;
    ((__half2*)&o)[0] = __hmax2(__hfma2(zp[0], scp[0], shp[0]), zero);
    ((__half2*)&o)[1] = __hmax2(__hfma2(zp[1], scp[1], shp[1]), zero);
    *(uint2*)(g_a + (size_t)row * KP + 4 * c4) = o;
}

// relu(z0h*sc2+sh2) -> g_hbuf, uint2-vectorized
__global__ void k_bnrelu() {
    gdep_wait();
    int idx = blockIdx.x * 256 + threadIdx.x;
    if (idx >= NN * 75) return;
    int row = idx / 75, c4 = idx - row * 75;
    uint2 z = *(const uint2*)(g_z0h + (size_t)row * DD + 4 * c4);
    uint2 scu = *(const uint2*)(g_sc2h + 4 * c4);
    uint2 shu = *(const uint2*)(g_sh2h + 4 * c4);
    __half2* zp = (__half2*)&z;
    __half2* scp = (__half2*)&scu;
    __half2* shp = (__half2*)&shu;
    __half2 zero = __floats2half2_rn(0.f, 0.f);
    uint2 o;
    ((__half2*)&o)[0] = __hmax2(__hfma2(zp[0], scp[0], shp[0]), zero);
    ((__half2*)&o)[1] = __hmax2(__hfma2(zp[1], scp[1], shp[1]), zero);
    *(uint2*)(g_hbuf + (size_t)row * KP + 4 * c4) = o;
}

// pool: read g_hbuf raw
__global__ void k_pool(int depth) {
    gdep_wait();
    int g = blockIdx.x;
    int c2 = blockIdx.y * 128 + threadIdx.x;
    if (c2 >= 150) return;
    int s0 = g_goff[g], s1 = g_goff[g + 1];
    s0 = max(0, min(NN, s0));
    s1 = max(s0, min(NN, s1));
    float ax = 0.f, ay = 0.f;
    for (int i = s0; i < s1; i++) {
        float2 f = __half22float2(*(const __half2*)(g_hbuf + (size_t)i * KP + 2 * c2));
        ax += f.x; ay += f.y;
    }
    float inv = 1.f / fmaxf((float)(s1 - s0), 1.f);
    float* pr = g_pooled + ((size_t)depth * NGR + g) * DD + 2 * c2;
    pr[0] = ax * inv;
    pr[1] = ay * inv;
}

__global__ void k_readout(const float* __restrict__ fcW, const float* __restrict__ fcb,
                          float* __restrict__ out) {
    gdep_wait();
    __shared__ float sp[DD];
    int g = blockIdx.x, c = threadIdx.x;
    float acc = 0.f;
    for (int d = 0; d <= LL; d++) {
        const float* pr = g_pooled + ((size_t)d * NGR + g) * DD;
        for (int f = c; f < DD; f += 128) sp[f] = pr[f];
        __syncthreads();
        const float* W = fcW + (size_t)d * DD * CC;
        float a = 0.f;
        #pragma unroll 4
        for (int k = 0; k < DD; k++) a += sp[k] * W[k * CC + c];
        acc += a + fcb[d * CC + c];
        __syncthreads();
    }
    out[g * CC + c] = acc;
}

// ---------------- PDL launch helper ----------------
template <class... A, class... B>
static void launch_pdl(void (*kern)(A...), dim3 g, dim3 b, size_t smem, B... args) {
    cudaLaunchConfig_t cfg = {};
    cfg.gridDim = g;
    cfg.blockDim = b;
    cfg.dynamicSmemBytes = smem;
    cfg.stream = 0;
    cudaLaunchAttribute at[1];
    at[0].id = cudaLaunchAttributeProgrammaticStreamSerialization;
    at[0].val.programmaticStreamSerializationAllowed = 1;
    cfg.attrs = at;
    cfg.numAttrs = 1;
    cudaLaunchKernelEx(&cfg, kern, (A)args...);
}

// ---------------- launch ----------------
extern "C" void kernel_launch(void* const* d_in, const int* in_sizes, int n_in,
                              void* d_out, int out_size) {
    const float* x     = (const float*)d_in[0];
    const void*  ei    = d_in[1];
    const void*  batch = d_in[2];
    const float* W1  = (const float*)d_in[3];
    const float* b1  = (const float*)d_in[4];
    const float* g1  = (const float*)d_in[5];
    const float* be1 = (const float*)d_in[6];
    const float* W2  = (const float*)d_in[7];
    const float* b2  = (const float*)d_in[8];
    const float* bng = (const float*)d_in[9];
    const float* bnb = (const float*)d_in[10];
    const float* fcW = (const float*)d_in[11];
    const float* fcb = (const float*)d_in[12];
    float* out = (float*)d_out;

    cudaFuncSetAttribute(k_gemm, cudaFuncAttributeMaxDynamicSharedMemorySize, SMEMSZ);

    launch_pdl(k_zero, dim3((NN + 255) / 256), dim3(256), 0, ei);
    launch_pdl(k_wprep, dim3(2 * LL * KP), dim3(WNP), 0, W1, b1, W2, b2);
    long long nxh = (long long)NN * KP2 + (long long)(NNP - NN) * KU4;
    launch_pdl(k_xhalf, dim3((int)((nxh + 255) / 256)), dim3(256), 0, x);
    launch_pdl(k_count, dim3((EE + 255) / 256), dim3(256), 0, ei);
    int nb = (NN + 511) / 512;
    launch_pdl(k_scan1, dim3(nb), dim3(512), 0);
    launch_pdl(k_scan2, dim3(1), dim3(128), 0, nb);
    launch_pdl(k_scan3, dim3((NN + 255) / 256), dim3(256), 0, batch);
    launch_pdl(k_fill, dim3((EE + 255) / 256), dim3(256), 0, ei);

    dim3 pg(NGR, 2);
    launch_pdl(k_pool, pg, dim3(128), 0, 0);

    dim3 gg(2, GRIDY);
    int bn_grid = (NN * 75 + 255) / 256;
    for (int i = 0; i < LL; i++) {
        launch_pdl(k_agg, dim3((NN + 7) / 8), dim3(256), 0);
        launch_pdl(k_gemm, gg, dim3(256), SMEMSZ, 2 * i, 0);
        launch_pdl(k_finalize, dim3(1), dim3(320), 0, 0, g1 + i * DD, be1 + i * DD);
        launch_pdl(k_bnsplit, dim3(bn_grid), dim3(256), 0);
        launch_pdl(k_gemm, gg, dim3(256), SMEMSZ, 2 * i + 1, 1);
        launch_pdl(k_finalize, dim3(1), dim3(320), 0, 1, bng + i * DD, bnb + i * DD);
        launch_pdl(k_bnrelu, dim3(bn_grid), dim3(256), 0);
        launch_pdl(k_pool, pg, dim3(128), 0, i + 1);
    }

    launch_pdl(k_readout, dim3(NGR), dim3(128), 0, fcW, fcb, out);
}